// round 16
// baseline (speedup 1.0000x reference)
#include <cuda_runtime.h>
#include <math.h>
#include <stdint.h>

#define Vn 65536
#define En 262144
#define Gn 2048
#define NPG 32
#define H 200
#define DEG 4
#define NODE_IN 74
#define EDGE_IN 12
#define NLAYERS 5
#define TT 2
#define H3 600
#define H2 400

typedef unsigned long long ull;

// ---------------- device scratch ----------------
__device__ float g_h[Vn * H];
__device__ float g_eh[En * H];
__device__ float g_gf[Gn * H];
__device__ float g_hbar[Gn * H];
__device__ float g_ctx[Gn * H];
__device__ float g_gi[Gn * H3];
__device__ float g_gh[Gn * H3];
// packed-pair weights for non-layer GEMMs
__device__ ull g_Wpr[TT * 100 * H];
__device__ ull g_Wnode[37 * H];
__device__ ull g_Wedge[6 * H];
__device__ ull g_Wih2[TT * 100 * H3];
__device__ ull g_Whh2[TT * 100 * H3];

// ---------------- packed f32x2 helpers ----------------
__device__ __forceinline__ ull pk2(float lo, float hi) {
    ull r;
    asm("mov.b64 %0, {%1, %2};" : "=l"(r) : "f"(lo), "f"(hi));
    return r;
}
__device__ __forceinline__ ull dup2(float v) {
    ull r;
    asm("mov.b64 %0, {%1, %1};" : "=l"(r) : "f"(v));
    return r;
}
__device__ __forceinline__ void fma2(ull& d, ull a, ull b) {
    asm("fma.rn.f32x2 %0, %1, %2, %0;" : "+l"(d) : "l"(a), "l"(b));
}
__device__ __forceinline__ float hsum2(ull v) {
    float x, y;
    asm("mov.b64 {%0, %1}, %2;" : "=f"(x), "=f"(y) : "l"(v));
    return x + y;
}
__device__ __forceinline__ void unpk2(float& lo, float& hi, ull v) {
    asm("mov.b64 {%0, %1}, %2;" : "=f"(lo), "=f"(hi) : "l"(v));
}

// ---------------- merged pack kernel (non-layer weights) ----------------
#define PK_PR   (TT * 100 * H)
#define PK_NODE (37 * H)
#define PK_EDGE (6 * H)
#define PK_GRU  (TT * 100 * H3)
#define PK_TOTAL (PK_PR + PK_NODE + PK_EDGE + PK_GRU)

__global__ void k_pack(const float* __restrict__ pr_W,
                       const float* __restrict__ node_W, const float* __restrict__ edge_W,
                       const float* __restrict__ W_ih, const float* __restrict__ W_hh) {
    int idx = blockIdx.x * blockDim.x + threadIdx.x;
    if (idx < PK_PR) {
        int k2 = idx / H, n = idx - k2 * H;
        g_Wpr[idx] = pk2(pr_W[(2 * k2) * H + n], pr_W[(2 * k2 + 1) * H + n]);
        return;
    }
    idx -= PK_PR;
    if (idx < PK_NODE) {
        int k2 = idx / H, n = idx - k2 * H;
        g_Wnode[idx] = pk2(node_W[(2 * k2) * H + n], node_W[(2 * k2 + 1) * H + n]);
        return;
    }
    idx -= PK_NODE;
    if (idx < PK_EDGE) {
        int k2 = idx / H, n = idx - k2 * H;
        g_Wedge[idx] = pk2(edge_W[(2 * k2) * H + n], edge_W[(2 * k2 + 1) * H + n]);
        return;
    }
    idx -= PK_EDGE;
    if (idx < PK_GRU) {
        int t = idx / (100 * H3);
        int r = idx - t * (100 * H3);
        int k2 = r / H3, j = r - k2 * H3;
        const float* wi = W_ih + t * H3 * H + j * H + 2 * k2;
        const float* wh = W_hh + t * H3 * H + j * H + 2 * k2;
        g_Wih2[idx] = pk2(wi[0], wi[1]);
        g_Whh2[idx] = pk2(wh[0], wh[1]);
    }
}

// ---------------- node embedding ----------------
__global__ __launch_bounds__(400, 2) void k_node_embed(const float* __restrict__ nf,
                                                       const float* __restrict__ b) {
    __shared__ __align__(16) float s[32][NODE_IN];
    int v0 = blockIdx.x * 32;
    int tid = threadIdx.x;
    for (int i = tid; i < 32 * NODE_IN; i += 400) {
        int r = i / NODE_IN, k = i - r * NODE_IN;
        s[r][k] = nf[(v0 + r) * NODE_IN + k];
    }
    __syncthreads();
    int q = tid / 200;
    int c = tid - q * 200;
    int r0 = q * 16;
    ull acc[16];
#pragma unroll
    for (int r = 0; r < 16; r++) acc[r] = 0ull;
    const ull* Wp = g_Wnode + c;
    for (int k2 = 0; k2 < 37; k2++) {
        ull w = __ldg(&Wp[k2 * H]);
#pragma unroll
        for (int r = 0; r < 16; r++) {
            ull a = *(const ull*)&s[r0 + r][2 * k2];
            fma2(acc[r], a, w);
        }
    }
    float bb = __ldg(&b[c]);
#pragma unroll
    for (int r = 0; r < 16; r++) g_h[(size_t)(v0 + r0 + r) * H + c] = hsum2(acc[r]) + bb;
}

// ---------------- edge embedding ----------------
__global__ __launch_bounds__(400, 2) void k_edge_embed(const float* __restrict__ ef,
                                                       const float* __restrict__ b) {
    __shared__ __align__(16) float s[32][EDGE_IN];
    int e0 = blockIdx.x * 32;
    int tid = threadIdx.x;
    for (int i = tid; i < 32 * EDGE_IN; i += 400) {
        int r = i / EDGE_IN, k = i - r * EDGE_IN;
        s[r][k] = ef[(e0 + r) * EDGE_IN + k];
    }
    __syncthreads();
    int q = tid / 200;
    int c = tid - q * 200;
    int r0 = q * 16;
    ull acc[16];
#pragma unroll
    for (int r = 0; r < 16; r++) acc[r] = 0ull;
    const ull* Wp = g_Wedge + c;
#pragma unroll
    for (int k2 = 0; k2 < 6; k2++) {
        ull w = __ldg(&Wp[k2 * H]);
#pragma unroll
        for (int r = 0; r < 16; r++) {
            ull a = *(const ull*)&s[r0 + r][2 * k2];
            fma2(acc[r], a, w);
        }
    }
    float bb = __ldg(&b[c]);
#pragma unroll
    for (int r = 0; r < 16; r++) g_eh[(size_t)(e0 + r0 + r) * H + c] = hsum2(acc[r]) + bb;
}

// ---------------- fused layer v10: warp = 32 rowpairs x 1 colgroup (W broadcast) ----------------
// block = 2 graphs (64 rows), 800 threads, 2 blocks/SM (50 warps).
// thread = 1 row-pair x 8 cols: A = 1 LDS.64 (256B/warp), W = 2 LDS.128 broadcast.
#define LROWS 64
#define PSTRIDE 34
#define KCHUNK 50
__global__ __launch_bounds__(800, 2) void k_layer(const int* __restrict__ src,
                                                  const float* __restrict__ W,
                                                  const float* __restrict__ bias) {
    extern __shared__ float smem[];
    float* s_w = smem;                                   // [50*200] floats (40 KB)
    ull* s_aggP = (ull*)(smem + KCHUNK * H);             // [200][34] ull (54.4 KB)
    int* s_src = (int*)(s_aggP + H * PSTRIDE);           // [256]

    int b = blockIdx.x;
    int tid = threadIdx.x;
    int vbase = b * LROWS;

    // phase 1: stage src (local indices)
    if (tid < LROWS * DEG) s_src[tid] = src[vbase * DEG + tid] - vbase;
    __syncthreads();

    // phase 2: edge softmax + aggregation (R11 scalar version — measured best)
    {
        int k = tid % 200;
        int quarter = tid / 200;                          // 0..3 -> rowpairs [8q, 8q+8)
        const float* ehb = g_eh + (size_t)vbase * DEG * H + k;
        const float* ghk = g_h + (size_t)vbase * H + k;
        for (int rp = quarter * 8; rp < quarter * 8 + 8; rp++) {
            float agg2[2];
#pragma unroll
            for (int hh = 0; hh < 2; hh++) {
                int e0 = (2 * rp + hh) * DEG;
                float m0 = __ldg(&ghk[s_src[e0 + 0] * H]) + __ldg(&ehb[(e0 + 0) * H]);
                float m1 = __ldg(&ghk[s_src[e0 + 1] * H]) + __ldg(&ehb[(e0 + 1) * H]);
                float m2 = __ldg(&ghk[s_src[e0 + 2] * H]) + __ldg(&ehb[(e0 + 2) * H]);
                float m3 = __ldg(&ghk[s_src[e0 + 3] * H]) + __ldg(&ehb[(e0 + 3) * H]);
                float mx = fmaxf(fmaxf(m0, m1), fmaxf(m2, m3));
                float e0x = __expf(m0 - mx), e1x = __expf(m1 - mx);
                float e2x = __expf(m2 - mx), e3x = __expf(m3 - mx);
                float den = e0x + e1x + e2x + e3x;
                agg2[hh] = (m0 * e0x + m1 * e1x + m2 * e2x + m3 * e3x) / den;
            }
            s_aggP[k * PSTRIDE + rp] = pk2(agg2[0], agg2[1]);
        }
    }

    // phase 3: GEMM; thread = 1 row-pair x 8 cols.
    // rpg = tid&31 (warp lanes = 32 consecutive rowpairs -> A LDS.64 256B contig),
    // cg = tid>>5 (constant per warp -> W LDS.128 uniform-address broadcast).
    int rpg = tid & 31;           // rowpair rpg, rows 2rpg, 2rpg+1
    int cg = tid >> 5;            // 0..24 -> cols [8cg, 8cg+8)
    int c0 = 8 * cg;

    ull acc[8];
#pragma unroll
    for (int c = 0; c < 8; c++) acc[c] = 0ull;

    for (int kc = 0; kc < H / KCHUNK; kc++) {
        __syncthreads();   // aggP ready (kc=0) / prior chunk consumed
        {
            const float4* wg4 = (const float4*)(W + kc * KCHUNK * H);
            float4* sw4 = (float4*)s_w;
#pragma unroll
            for (int i = 0; i < 3; i++) sw4[tid + i * 800] = wg4[tid + i * 800];
            if (tid < 100) sw4[2400 + tid] = wg4[2400 + tid];
        }
        __syncthreads();
        const ull* apk = s_aggP + (size_t)(kc * KCHUNK) * PSTRIDE + rpg;
        const float* swc = s_w + c0;
#pragma unroll 2
        for (int kk = 0; kk < KCHUNK; kk++) {
            float4 wA = *(const float4*)(swc + kk * H);          // uniform addr per warp
            float4 wB = *(const float4*)(swc + kk * H + 4);      // uniform addr per warp
            ull a = apk[kk * PSTRIDE];                           // LDS.64, 256B contig/warp
            fma2(acc[0], a, dup2(wA.x)); fma2(acc[1], a, dup2(wA.y));
            fma2(acc[2], a, dup2(wA.z)); fma2(acc[3], a, dup2(wA.w));
            fma2(acc[4], a, dup2(wB.x)); fma2(acc[5], a, dup2(wB.y));
            fma2(acc[6], a, dup2(wB.z)); fma2(acc[7], a, dup2(wB.w));
        }
    }

    // phase 4: h = relu(D + bias) + h_old (residual re-read from gmem; rows owned by block)
    {
        float4 bbA = *(const float4*)(bias + c0);
        float4 bbB = *(const float4*)(bias + c0 + 4);
        float lo[8], hi[8];
#pragma unroll
        for (int c = 0; c < 8; c++) unpk2(lo[c], hi[c], acc[c]);
        float* gp0 = g_h + (size_t)(vbase + 2 * rpg) * H + c0;
        float* gp1 = gp0 + H;
        float4 h0a = *(const float4*)gp0;
        float4 h0b = *(const float4*)(gp0 + 4);
        float4 h1a = *(const float4*)gp1;
        float4 h1b = *(const float4*)(gp1 + 4);
        float4 o0a, o0b, o1a, o1b;
        o0a.x = fmaxf(lo[0] + bbA.x, 0.f) + h0a.x;
        o0a.y = fmaxf(lo[1] + bbA.y, 0.f) + h0a.y;
        o0a.z = fmaxf(lo[2] + bbA.z, 0.f) + h0a.z;
        o0a.w = fmaxf(lo[3] + bbA.w, 0.f) + h0a.w;
        o0b.x = fmaxf(lo[4] + bbB.x, 0.f) + h0b.x;
        o0b.y = fmaxf(lo[5] + bbB.y, 0.f) + h0b.y;
        o0b.z = fmaxf(lo[6] + bbB.z, 0.f) + h0b.z;
        o0b.w = fmaxf(lo[7] + bbB.w, 0.f) + h0b.w;
        o1a.x = fmaxf(hi[0] + bbA.x, 0.f) + h1a.x;
        o1a.y = fmaxf(hi[1] + bbA.y, 0.f) + h1a.y;
        o1a.z = fmaxf(hi[2] + bbA.z, 0.f) + h1a.z;
        o1a.w = fmaxf(hi[3] + bbA.w, 0.f) + h1a.w;
        o1b.x = fmaxf(hi[4] + bbB.x, 0.f) + h1b.x;
        o1b.y = fmaxf(hi[5] + bbB.y, 0.f) + h1b.y;
        o1b.z = fmaxf(hi[6] + bbB.z, 0.f) + h1b.z;
        o1b.w = fmaxf(hi[7] + bbB.w, 0.f) + h1b.w;
        *(float4*)gp0 = o0a;
        *(float4*)(gp0 + 4) = o0b;
        *(float4*)gp1 = o1a;
        *(float4*)(gp1 + 4) = o1b;
    }
}

// ---------------- gf init ----------------
__global__ __launch_bounds__(200) void k_gf() {
    int g = blockIdx.x, c = threadIdx.x;
    float sum = 0.f;
    int base = g * NPG * H + c;
    for (int i = 0; i < NPG; i++) sum += g_h[base + i * H];
    g_gf[g * H + c] = sum;
}

// ---------------- fused readout attention + hbar ----------------
__global__ __launch_bounds__(256) void k_zhbar(const float* __restrict__ lgW,
                                               const float* __restrict__ lgb, int t) {
    const float* w = lgW + t * H2;
    float bb = __ldg(&lgb[t]);
    int g = blockIdx.x;
    int tid = threadIdx.x;
    __shared__ __align__(16) float s_h[NPG * H];
    __shared__ float red[256];
    __shared__ float zs[NPG];

    {
        const float4* gh4 = (const float4*)(g_h + (size_t)g * NPG * H);
        float4* sh4 = (float4*)s_h;
        for (int i = tid; i < NPG * H / 4; i += 256) sh4[i] = gh4[i];
    }

    float p = 0.f;
    if (tid < H) {
        float gfv = g_gf[g * H + tid];
        gfv = gfv > 0.f ? gfv : 0.f;
        p = gfv * w[tid];
    }
    red[tid] = p;
    __syncthreads();
    for (int off = 128; off > 0; off >>= 1) {
        if (tid < off) red[tid] += red[tid + off];
        __syncthreads();
    }
    float sg = red[0];

    int warp = tid >> 5, lane = tid & 31;
    for (int n = warp; n < NPG; n += 8) {
        float sum = 0.f;
        for (int c = lane; c < H; c += 32) sum += s_h[n * H + c] * w[H + c];
        for (int off = 16; off; off >>= 1) sum += __shfl_xor_sync(0xffffffffu, sum, off);
        if (lane == 0) {
            float z = sum + sg + bb;
            zs[n] = z > 0.f ? z : 0.01f * z;
        }
    }
    __syncthreads();
    if (tid < 32) {
        float zv = zs[tid];
        float mx = zv;
        for (int off = 16; off; off >>= 1) mx = fmaxf(mx, __shfl_xor_sync(0xffffffffu, mx, off));
        float e = __expf(zv - mx);
        float den = e;
        for (int off = 16; off; off >>= 1) den += __shfl_xor_sync(0xffffffffu, den, off);
        zs[tid] = e / den;
    }
    __syncthreads();
    if (tid < H) {
        float sum = 0.f;
#pragma unroll 8
        for (int v = 0; v < NPG; v++) sum += zs[v] * s_h[v * H + tid];
        g_hbar[g * H + tid] = sum;
    }
}

// ---------------- ctx ----------------
__global__ __launch_bounds__(400, 2) void k_ctx(const float* __restrict__ prb, int t) {
    __shared__ __align__(16) float s[32][H];
    int g0 = blockIdx.x * 32;
    int tid = threadIdx.x;
    for (int i = tid; i < 32 * H; i += 400) {
        int r = i / H, k = i - r * H;
        s[r][k] = g_hbar[(g0 + r) * H + k];
    }
    __syncthreads();
    int q = tid / 200;
    int c = tid - q * 200;
    int r0 = q * 16;
    ull acc[16];
#pragma unroll
    for (int r = 0; r < 16; r++) acc[r] = 0ull;
    const ull* Wp = g_Wpr + (size_t)t * 100 * H + c;
    for (int k = 0; k < H; k += 4) {
        int k2 = k >> 1;
        ull w01 = __ldg(&Wp[k2 * H]);
        ull w23 = __ldg(&Wp[(k2 + 1) * H]);
#pragma unroll
        for (int r = 0; r < 16; r++) {
            ulonglong2 a = *(const ulonglong2*)&s[r0 + r][k];
            fma2(acc[r], a.x, w01);
            fma2(acc[r], a.y, w23);
        }
    }
    float bb = __ldg(&prb[t * H + c]);
#pragma unroll
    for (int r = 0; r < 16; r++) {
        float o = hsum2(acc[r]) + bb;
        o = o > 0.f ? o : expm1f(o);
        g_ctx[(size_t)(g0 + r0 + r) * H + c] = o;
    }
}

// ---------------- GRU gate GEMMs ----------------
__global__ __launch_bounds__(600) void k_gru(const float* __restrict__ bih,
                                             const float* __restrict__ bhh, int t) {
    __shared__ __align__(16) float sc[8][H];
    __shared__ __align__(16) float sh[8][H];
    int g0 = blockIdx.x * 8;
    int tid = threadIdx.x;
    for (int i = tid; i < 8 * H; i += 600) {
        int r = i / H, k = i - r * H;
        sc[r][k] = g_ctx[(g0 + r) * H + k];
        sh[r][k] = g_gf[(g0 + r) * H + k];
    }
    __syncthreads();
    int j = tid;
    const ull* Wi = g_Wih2 + (size_t)t * 100 * H3 + j;
    const ull* Wh = g_Whh2 + (size_t)t * 100 * H3 + j;
    ull ai[8], ah[8];
#pragma unroll
    for (int r = 0; r < 8; r++) { ai[r] = 0ull; ah[r] = 0ull; }
    for (int k = 0; k < H; k += 4) {
        int k2 = k >> 1;
        ull wi01 = __ldg(&Wi[k2 * H3]);
        ull wi23 = __ldg(&Wi[(k2 + 1) * H3]);
        ull wh01 = __ldg(&Wh[k2 * H3]);
        ull wh23 = __ldg(&Wh[(k2 + 1) * H3]);
#pragma unroll
        for (int r = 0; r < 8; r++) {
            ulonglong2 a = *(const ulonglong2*)&sc[r][k];
            fma2(ai[r], a.x, wi01);
            fma2(ai[r], a.y, wi23);
            ulonglong2 h4 = *(const ulonglong2*)&sh[r][k];
            fma2(ah[r], h4.x, wh01);
            fma2(ah[r], h4.y, wh23);
        }
    }
    float bi = __ldg(&bih[t * H3 + j]);
    float bh = __ldg(&bhh[t * H3 + j]);
#pragma unroll
    for (int r = 0; r < 8; r++) {
        g_gi[(size_t)(g0 + r) * H3 + j] = hsum2(ai[r]) + bi;
        g_gh[(size_t)(g0 + r) * H3 + j] = hsum2(ah[r]) + bh;
    }
}

// ---------------- GRU combine ----------------
__global__ __launch_bounds__(200) void k_gate() {
    int g = blockIdx.x, c = threadIdx.x;
    int base = g * H3;
    float ir = g_gi[base + c],          hr = g_gh[base + c];
    float iz = g_gi[base + H + c],      hz = g_gh[base + H + c];
    float in_ = g_gi[base + 2 * H + c], hn = g_gh[base + 2 * H + c];
    float r = 1.f / (1.f + expf(-(ir + hr)));
    float u = 1.f / (1.f + expf(-(iz + hz)));
    float n = tanhf(in_ + r * hn);
    int o = g * H + c;
    g_gf[o] = (1.f - u) * n + u * g_gf[o];
}

// ---------------- copy result ----------------
__global__ void k_copy(float* __restrict__ out, int n) {
    int i = blockIdx.x * blockDim.x + threadIdx.x;
    if (i < n) out[i] = g_gf[i];
}

// ---------------- launcher ----------------
extern "C" void kernel_launch(void* const* d_in, const int* in_sizes, int n_in,
                              void* d_out, int out_size) {
    const float* node_feat = (const float*)d_in[0];
    const float* edge_feat = (const float*)d_in[1];
    const int*   src       = (const int*)d_in[2];
    const float* node_W = (const float*)d_in[5];
    const float* node_b = (const float*)d_in[6];
    const float* edge_W = (const float*)d_in[7];
    const float* edge_b = (const float*)d_in[8];
    const float* gnn_W  = (const float*)d_in[9];
    const float* gnn_b  = (const float*)d_in[10];
    const float* lg_W   = (const float*)d_in[11];
    const float* lg_b   = (const float*)d_in[12];
    const float* pr_W   = (const float*)d_in[13];
    const float* pr_b   = (const float*)d_in[14];
    const float* W_ih   = (const float*)d_in[15];
    const float* W_hh   = (const float*)d_in[16];
    const float* b_ih   = (const float*)d_in[17];
    const float* b_hh   = (const float*)d_in[18];

    // smem: s_w 40 KB + aggP 54.4 KB + src 1 KB = 95.4 KB -> 2 blocks/SM
    const int SMEM_LAYER = KCHUNK * H * 4 + H * PSTRIDE * 8 + LROWS * DEG * 4;
    cudaFuncSetAttribute(k_layer, cudaFuncAttributeMaxDynamicSharedMemorySize, SMEM_LAYER);

    k_pack<<<(PK_TOTAL + 255) / 256, 256>>>(pr_W, node_W, edge_W, W_ih, W_hh);
    k_node_embed<<<Vn / 32, 400>>>(node_feat, node_b);
    k_edge_embed<<<En / 32, 400>>>(edge_feat, edge_b);

    // launches 3-7: layers (launch index 5 = layer #2 for ncu -s 5)
    for (int i = 0; i < NLAYERS; i++) {
        k_layer<<<Vn / LROWS, 800, SMEM_LAYER>>>(src, gnn_W + i * H * H, gnn_b + i * H);
    }

    k_gf<<<Gn, 200>>>();
    for (int t = 0; t < TT; t++) {
        k_zhbar<<<Gn, 256>>>(lg_W, lg_b, t);
        k_ctx<<<Gn / 32, 400>>>(pr_b, t);
        k_gru<<<Gn / 8, 600>>>(b_ih, b_hh, t);
        k_gate<<<Gn, 200>>>();
    }

    k_copy<<<(Gn * H + 255) / 256, 256>>>((float*)d_out, Gn * H);
}

// round 17
// speedup vs baseline: 1.2484x; 1.2484x over previous
#include <cuda_runtime.h>
#include <math.h>
#include <stdint.h>

#define Vn 65536
#define En 262144
#define Gn 2048
#define NPG 32
#define H 200
#define DEG 4
#define NODE_IN 74
#define EDGE_IN 12
#define NLAYERS 5
#define TT 2
#define H3 600
#define H2 400

typedef unsigned long long ull;

// ---------------- device scratch ----------------
__device__ float g_h[Vn * H];
__device__ float g_eh[En * H];
__device__ float g_gf[Gn * H];
__device__ float g_hbar[Gn * H];
__device__ float g_ctx[Gn * H];
__device__ float g_gi[Gn * H3];
__device__ float g_gh[Gn * H3];
// packed-pair weights for non-layer GEMMs
__device__ ull g_Wpr[TT * 100 * H];
__device__ ull g_Wnode[37 * H];
__device__ ull g_Wedge[6 * H];
__device__ ull g_Wih2[TT * 100 * H3];
__device__ ull g_Whh2[TT * 100 * H3];

// ---------------- packed f32x2 helpers ----------------
__device__ __forceinline__ ull pk2(float lo, float hi) {
    ull r;
    asm("mov.b64 %0, {%1, %2};" : "=l"(r) : "f"(lo), "f"(hi));
    return r;
}
__device__ __forceinline__ ull dup2(float v) {
    ull r;
    asm("mov.b64 %0, {%1, %1};" : "=l"(r) : "f"(v));
    return r;
}
__device__ __forceinline__ void fma2(ull& d, ull a, ull b) {
    asm("fma.rn.f32x2 %0, %1, %2, %0;" : "+l"(d) : "l"(a), "l"(b));
}
__device__ __forceinline__ float hsum2(ull v) {
    float x, y;
    asm("mov.b64 {%0, %1}, %2;" : "=f"(x), "=f"(y) : "l"(v));
    return x + y;
}
__device__ __forceinline__ void unpk2(float& lo, float& hi, ull v) {
    asm("mov.b64 {%0, %1}, %2;" : "=f"(lo), "=f"(hi) : "l"(v));
}

// ---------------- merged pack kernel (non-layer weights) ----------------
#define PK_PR   (TT * 100 * H)
#define PK_NODE (37 * H)
#define PK_EDGE (6 * H)
#define PK_GRU  (TT * 100 * H3)
#define PK_TOTAL (PK_PR + PK_NODE + PK_EDGE + PK_GRU)

__global__ void k_pack(const float* __restrict__ pr_W,
                       const float* __restrict__ node_W, const float* __restrict__ edge_W,
                       const float* __restrict__ W_ih, const float* __restrict__ W_hh) {
    int idx = blockIdx.x * blockDim.x + threadIdx.x;
    if (idx < PK_PR) {
        int k2 = idx / H, n = idx - k2 * H;
        g_Wpr[idx] = pk2(pr_W[(2 * k2) * H + n], pr_W[(2 * k2 + 1) * H + n]);
        return;
    }
    idx -= PK_PR;
    if (idx < PK_NODE) {
        int k2 = idx / H, n = idx - k2 * H;
        g_Wnode[idx] = pk2(node_W[(2 * k2) * H + n], node_W[(2 * k2 + 1) * H + n]);
        return;
    }
    idx -= PK_NODE;
    if (idx < PK_EDGE) {
        int k2 = idx / H, n = idx - k2 * H;
        g_Wedge[idx] = pk2(edge_W[(2 * k2) * H + n], edge_W[(2 * k2 + 1) * H + n]);
        return;
    }
    idx -= PK_EDGE;
    if (idx < PK_GRU) {
        int t = idx / (100 * H3);
        int r = idx - t * (100 * H3);
        int k2 = r / H3, j = r - k2 * H3;
        const float* wi = W_ih + t * H3 * H + j * H + 2 * k2;
        const float* wh = W_hh + t * H3 * H + j * H + 2 * k2;
        g_Wih2[idx] = pk2(wi[0], wi[1]);
        g_Whh2[idx] = pk2(wh[0], wh[1]);
    }
}

// ---------------- node embedding ----------------
__global__ __launch_bounds__(400, 2) void k_node_embed(const float* __restrict__ nf,
                                                       const float* __restrict__ b) {
    __shared__ __align__(16) float s[32][NODE_IN];
    int v0 = blockIdx.x * 32;
    int tid = threadIdx.x;
    for (int i = tid; i < 32 * NODE_IN; i += 400) {
        int r = i / NODE_IN, k = i - r * NODE_IN;
        s[r][k] = nf[(v0 + r) * NODE_IN + k];
    }
    __syncthreads();
    int q = tid / 200;
    int c = tid - q * 200;
    int r0 = q * 16;
    ull acc[16];
#pragma unroll
    for (int r = 0; r < 16; r++) acc[r] = 0ull;
    const ull* Wp = g_Wnode + c;
    for (int k2 = 0; k2 < 37; k2++) {
        ull w = __ldg(&Wp[k2 * H]);
#pragma unroll
        for (int r = 0; r < 16; r++) {
            ull a = *(const ull*)&s[r0 + r][2 * k2];
            fma2(acc[r], a, w);
        }
    }
    float bb = __ldg(&b[c]);
#pragma unroll
    for (int r = 0; r < 16; r++) g_h[(size_t)(v0 + r0 + r) * H + c] = hsum2(acc[r]) + bb;
}

// ---------------- edge embedding ----------------
__global__ __launch_bounds__(400, 2) void k_edge_embed(const float* __restrict__ ef,
                                                       const float* __restrict__ b) {
    __shared__ __align__(16) float s[32][EDGE_IN];
    int e0 = blockIdx.x * 32;
    int tid = threadIdx.x;
    for (int i = tid; i < 32 * EDGE_IN; i += 400) {
        int r = i / EDGE_IN, k = i - r * EDGE_IN;
        s[r][k] = ef[(e0 + r) * EDGE_IN + k];
    }
    __syncthreads();
    int q = tid / 200;
    int c = tid - q * 200;
    int r0 = q * 16;
    ull acc[16];
#pragma unroll
    for (int r = 0; r < 16; r++) acc[r] = 0ull;
    const ull* Wp = g_Wedge + c;
#pragma unroll
    for (int k2 = 0; k2 < 6; k2++) {
        ull w = __ldg(&Wp[k2 * H]);
#pragma unroll
        for (int r = 0; r < 16; r++) {
            ull a = *(const ull*)&s[r0 + r][2 * k2];
            fma2(acc[r], a, w);
        }
    }
    float bb = __ldg(&b[c]);
#pragma unroll
    for (int r = 0; r < 16; r++) g_eh[(size_t)(e0 + r0 + r) * H + c] = hsum2(acc[r]) + bb;
}

// ---------------- fused layer v5 (measured best) + phase-2 unroll ----------------
// block = 2 graphs (64 rows), 800 threads, 2 blocks/SM (50 warps).
// GEMM thread = 2 row-pairs x 4 cols, mapping rg = tid/50, cg = tid%50.
#define LROWS 64
#define PSTRIDE 34
#define KCHUNK 50
__global__ __launch_bounds__(800, 2) void k_layer(const int* __restrict__ src,
                                                  const float* __restrict__ W,
                                                  const float* __restrict__ bias) {
    extern __shared__ float smem[];
    float* s_w = smem;                                   // [50*200] floats (40 KB)
    ull* s_aggP = (ull*)(smem + KCHUNK * H);             // [200][34] ull (54.4 KB)
    int* s_src = (int*)(s_aggP + H * PSTRIDE);           // [256]

    int b = blockIdx.x;
    int tid = threadIdx.x;
    int vbase = b * LROWS;

    // phase 1: stage src (local indices)
    if (tid < LROWS * DEG) s_src[tid] = src[vbase * DEG + tid] - vbase;
    __syncthreads();

    // phase 2: edge softmax + aggregation; h gathered from gmem (L1/L2, coalesced)
    {
        int k = tid % 200;
        int quarter = tid / 200;                          // 0..3 -> rowpairs [8q, 8q+8)
        const float* ehb = g_eh + (size_t)vbase * DEG * H + k;
        const float* ghk = g_h + (size_t)vbase * H + k;
#pragma unroll 2
        for (int rp = quarter * 8; rp < quarter * 8 + 8; rp++) {
            float agg2[2];
#pragma unroll
            for (int hh = 0; hh < 2; hh++) {
                int e0 = (2 * rp + hh) * DEG;
                float m0 = __ldg(&ghk[s_src[e0 + 0] * H]) + __ldg(&ehb[(e0 + 0) * H]);
                float m1 = __ldg(&ghk[s_src[e0 + 1] * H]) + __ldg(&ehb[(e0 + 1) * H]);
                float m2 = __ldg(&ghk[s_src[e0 + 2] * H]) + __ldg(&ehb[(e0 + 2) * H]);
                float m3 = __ldg(&ghk[s_src[e0 + 3] * H]) + __ldg(&ehb[(e0 + 3) * H]);
                float mx = fmaxf(fmaxf(m0, m1), fmaxf(m2, m3));
                float e0x = __expf(m0 - mx), e1x = __expf(m1 - mx);
                float e2x = __expf(m2 - mx), e3x = __expf(m3 - mx);
                float den = e0x + e1x + e2x + e3x;
                agg2[hh] = (m0 * e0x + m1 * e1x + m2 * e2x + m3 * e3x) / den;
            }
            s_aggP[k * PSTRIDE + rp] = pk2(agg2[0], agg2[1]);
        }
    }

    // phase 3: GEMM, thread = 2 row-pairs x 4 cols, W staged per 50-k chunk
    int rg = tid / 50;            // 0..15 -> rowpairs [2rg, 2rg+2), rows [4rg, 4rg+4)
    int cg = tid - rg * 50;       // 0..49 -> cols [4cg, 4cg+4)
    int c0 = 4 * cg;
    int rp0 = 2 * rg;

    ull acc[2][4];
#pragma unroll
    for (int j = 0; j < 2; j++)
#pragma unroll
        for (int c = 0; c < 4; c++) acc[j][c] = 0ull;

    for (int kc = 0; kc < H / KCHUNK; kc++) {
        __syncthreads();   // aggP ready (kc=0) / prior chunk consumed
        {
            const float4* wg4 = (const float4*)(W + kc * KCHUNK * H);
            float4* sw4 = (float4*)s_w;
#pragma unroll
            for (int i = 0; i < 3; i++) sw4[tid + i * 800] = wg4[tid + i * 800];
            if (tid < 100) sw4[2400 + tid] = wg4[2400 + tid];
        }
        __syncthreads();
        const ull* apk = s_aggP + (size_t)(kc * KCHUNK) * PSTRIDE + rp0;
        const float* swc = s_w + c0;
#pragma unroll 2
        for (int kk = 0; kk < KCHUNK; kk++) {
            float4 w = *(const float4*)(swc + kk * H);              // LDS.128
            ull wd0 = dup2(w.x), wd1 = dup2(w.y), wd2 = dup2(w.z), wd3 = dup2(w.w);
            ulonglong2 a = *(const ulonglong2*)(apk + kk * PSTRIDE); // LDS.128 broadcast
            fma2(acc[0][0], a.x, wd0); fma2(acc[0][1], a.x, wd1);
            fma2(acc[0][2], a.x, wd2); fma2(acc[0][3], a.x, wd3);
            fma2(acc[1][0], a.y, wd0); fma2(acc[1][1], a.y, wd1);
            fma2(acc[1][2], a.y, wd2); fma2(acc[1][3], a.y, wd3);
        }
    }

    // phase 4: h = relu(D + bias) + h_old (residual re-read from gmem; rows owned by block)
    float4 bb = *(const float4*)(bias + c0);
#pragma unroll
    for (int j = 0; j < 2; j++) {
        int row0 = 4 * rg + 2 * j;
        float lo0, hi0, lo1, hi1, lo2, hi2, lo3, hi3;
        unpk2(lo0, hi0, acc[j][0]);
        unpk2(lo1, hi1, acc[j][1]);
        unpk2(lo2, hi2, acc[j][2]);
        unpk2(lo3, hi3, acc[j][3]);
        float* gp0 = g_h + (size_t)(vbase + row0) * H + c0;
        float* gp1 = gp0 + H;
        float4 h0 = *(const float4*)gp0;
        float4 h1 = *(const float4*)gp1;
        float4 o0, o1;
        o0.x = fmaxf(lo0 + bb.x, 0.f) + h0.x;
        o0.y = fmaxf(lo1 + bb.y, 0.f) + h0.y;
        o0.z = fmaxf(lo2 + bb.z, 0.f) + h0.z;
        o0.w = fmaxf(lo3 + bb.w, 0.f) + h0.w;
        o1.x = fmaxf(hi0 + bb.x, 0.f) + h1.x;
        o1.y = fmaxf(hi1 + bb.y, 0.f) + h1.y;
        o1.z = fmaxf(hi2 + bb.z, 0.f) + h1.z;
        o1.w = fmaxf(hi3 + bb.w, 0.f) + h1.w;
        *(float4*)gp0 = o0;
        *(float4*)gp1 = o1;
    }
}

// ---------------- fused readout attention + hbar (+ gf init when first) ----------------
__global__ __launch_bounds__(256) void k_zhbar(const float* __restrict__ lgW,
                                               const float* __restrict__ lgb, int t,
                                               int first) {
    const float* w = lgW + t * H2;
    float bb = __ldg(&lgb[t]);
    int g = blockIdx.x;
    int tid = threadIdx.x;
    __shared__ __align__(16) float s_h[NPG * H];
    __shared__ float red[256];
    __shared__ float zs[NPG];

    {
        const float4* gh4 = (const float4*)(g_h + (size_t)g * NPG * H);
        float4* sh4 = (float4*)s_h;
        for (int i = tid; i < NPG * H / 4; i += 256) sh4[i] = gh4[i];
    }
    __syncthreads();

    float gfv = 0.f;
    if (tid < H) {
        if (first) {
            float s = 0.f;
#pragma unroll 8
            for (int v = 0; v < NPG; v++) s += s_h[v * H + tid];
            g_gf[g * H + tid] = s;   // initialize gf for GRU
            gfv = s;
        } else {
            gfv = g_gf[g * H + tid];
        }
    }

    float p = 0.f;
    if (tid < H) {
        float gfr = gfv > 0.f ? gfv : 0.f;
        p = gfr * w[tid];
    }
    red[tid] = p;
    __syncthreads();
    for (int off = 128; off > 0; off >>= 1) {
        if (tid < off) red[tid] += red[tid + off];
        __syncthreads();
    }
    float sg = red[0];

    int warp = tid >> 5, lane = tid & 31;
    for (int n = warp; n < NPG; n += 8) {
        float sum = 0.f;
        for (int c = lane; c < H; c += 32) sum += s_h[n * H + c] * w[H + c];
        for (int off = 16; off; off >>= 1) sum += __shfl_xor_sync(0xffffffffu, sum, off);
        if (lane == 0) {
            float z = sum + sg + bb;
            zs[n] = z > 0.f ? z : 0.01f * z;
        }
    }
    __syncthreads();
    if (tid < 32) {
        float zv = zs[tid];
        float mx = zv;
        for (int off = 16; off; off >>= 1) mx = fmaxf(mx, __shfl_xor_sync(0xffffffffu, mx, off));
        float e = __expf(zv - mx);
        float den = e;
        for (int off = 16; off; off >>= 1) den += __shfl_xor_sync(0xffffffffu, den, off);
        zs[tid] = e / den;
    }
    __syncthreads();
    if (tid < H) {
        float sum = 0.f;
#pragma unroll 8
        for (int v = 0; v < NPG; v++) sum += zs[v] * s_h[v * H + tid];
        g_hbar[g * H + tid] = sum;
    }
}

// ---------------- ctx ----------------
__global__ __launch_bounds__(400, 2) void k_ctx(const float* __restrict__ prb, int t) {
    __shared__ __align__(16) float s[32][H];
    int g0 = blockIdx.x * 32;
    int tid = threadIdx.x;
    for (int i = tid; i < 32 * H; i += 400) {
        int r = i / H, k = i - r * H;
        s[r][k] = g_hbar[(g0 + r) * H + k];
    }
    __syncthreads();
    int q = tid / 200;
    int c = tid - q * 200;
    int r0 = q * 16;
    ull acc[16];
#pragma unroll
    for (int r = 0; r < 16; r++) acc[r] = 0ull;
    const ull* Wp = g_Wpr + (size_t)t * 100 * H + c;
    for (int k = 0; k < H; k += 4) {
        int k2 = k >> 1;
        ull w01 = __ldg(&Wp[k2 * H]);
        ull w23 = __ldg(&Wp[(k2 + 1) * H]);
#pragma unroll
        for (int r = 0; r < 16; r++) {
            ulonglong2 a = *(const ulonglong2*)&s[r0 + r][k];
            fma2(acc[r], a.x, w01);
            fma2(acc[r], a.y, w23);
        }
    }
    float bb = __ldg(&prb[t * H + c]);
#pragma unroll
    for (int r = 0; r < 16; r++) {
        float o = hsum2(acc[r]) + bb;
        o = o > 0.f ? o : expm1f(o);
        g_ctx[(size_t)(g0 + r0 + r) * H + c] = o;
    }
}

// ---------------- GRU gate GEMMs ----------------
__global__ __launch_bounds__(600) void k_gru(const float* __restrict__ bih,
                                             const float* __restrict__ bhh, int t) {
    __shared__ __align__(16) float sc[8][H];
    __shared__ __align__(16) float sh[8][H];
    int g0 = blockIdx.x * 8;
    int tid = threadIdx.x;
    for (int i = tid; i < 8 * H; i += 600) {
        int r = i / H, k = i - r * H;
        sc[r][k] = g_ctx[(g0 + r) * H + k];
        sh[r][k] = g_gf[(g0 + r) * H + k];
    }
    __syncthreads();
    int j = tid;
    const ull* Wi = g_Wih2 + (size_t)t * 100 * H3 + j;
    const ull* Wh = g_Whh2 + (size_t)t * 100 * H3 + j;
    ull ai[8], ah[8];
#pragma unroll
    for (int r = 0; r < 8; r++) { ai[r] = 0ull; ah[r] = 0ull; }
    for (int k = 0; k < H; k += 4) {
        int k2 = k >> 1;
        ull wi01 = __ldg(&Wi[k2 * H3]);
        ull wi23 = __ldg(&Wi[(k2 + 1) * H3]);
        ull wh01 = __ldg(&Wh[k2 * H3]);
        ull wh23 = __ldg(&Wh[(k2 + 1) * H3]);
#pragma unroll
        for (int r = 0; r < 8; r++) {
            ulonglong2 a = *(const ulonglong2*)&sc[r][k];
            fma2(ai[r], a.x, wi01);
            fma2(ai[r], a.y, wi23);
            ulonglong2 h4 = *(const ulonglong2*)&sh[r][k];
            fma2(ah[r], h4.x, wh01);
            fma2(ah[r], h4.y, wh23);
        }
    }
    float bi = __ldg(&bih[t * H3 + j]);
    float bh = __ldg(&bhh[t * H3 + j]);
#pragma unroll
    for (int r = 0; r < 8; r++) {
        g_gi[(size_t)(g0 + r) * H3 + j] = hsum2(ai[r]) + bi;
        g_gh[(size_t)(g0 + r) * H3 + j] = hsum2(ah[r]) + bh;
    }
}

// ---------------- GRU combine ----------------
__global__ __launch_bounds__(200) void k_gate() {
    int g = blockIdx.x, c = threadIdx.x;
    int base = g * H3;
    float ir = g_gi[base + c],          hr = g_gh[base + c];
    float iz = g_gi[base + H + c],      hz = g_gh[base + H + c];
    float in_ = g_gi[base + 2 * H + c], hn = g_gh[base + 2 * H + c];
    float r = 1.f / (1.f + expf(-(ir + hr)));
    float u = 1.f / (1.f + expf(-(iz + hz)));
    float n = tanhf(in_ + r * hn);
    int o = g * H + c;
    g_gf[o] = (1.f - u) * n + u * g_gf[o];
}

// ---------------- copy result ----------------
__global__ void k_copy(float* __restrict__ out, int n) {
    int i = blockIdx.x * blockDim.x + threadIdx.x;
    if (i < n) out[i] = g_gf[i];
}

// ---------------- launcher ----------------
extern "C" void kernel_launch(void* const* d_in, const int* in_sizes, int n_in,
                              void* d_out, int out_size) {
    const float* node_feat = (const float*)d_in[0];
    const float* edge_feat = (const float*)d_in[1];
    const int*   src       = (const int*)d_in[2];
    const float* node_W = (const float*)d_in[5];
    const float* node_b = (const float*)d_in[6];
    const float* edge_W = (const float*)d_in[7];
    const float* edge_b = (const float*)d_in[8];
    const float* gnn_W  = (const float*)d_in[9];
    const float* gnn_b  = (const float*)d_in[10];
    const float* lg_W   = (const float*)d_in[11];
    const float* lg_b   = (const float*)d_in[12];
    const float* pr_W   = (const float*)d_in[13];
    const float* pr_b   = (const float*)d_in[14];
    const float* W_ih   = (const float*)d_in[15];
    const float* W_hh   = (const float*)d_in[16];
    const float* b_ih   = (const float*)d_in[17];
    const float* b_hh   = (const float*)d_in[18];

    // smem: s_w 40 KB + aggP 54.4 KB + src 1 KB = 95.4 KB -> 2 blocks/SM
    const int SMEM_LAYER = KCHUNK * H * 4 + H * PSTRIDE * 8 + LROWS * DEG * 4;
    cudaFuncSetAttribute(k_layer, cudaFuncAttributeMaxDynamicSharedMemorySize, SMEM_LAYER);

    k_pack<<<(PK_TOTAL + 255) / 256, 256>>>(pr_W, node_W, edge_W, W_ih, W_hh);
    k_node_embed<<<Vn / 32, 400>>>(node_feat, node_b);
    k_edge_embed<<<En / 32, 400>>>(edge_feat, edge_b);

    // launches 3-7: layers (launch index 5 = layer #2 for ncu -s 5)
    for (int i = 0; i < NLAYERS; i++) {
        k_layer<<<Vn / LROWS, 800, SMEM_LAYER>>>(src, gnn_W + i * H * H, gnn_b + i * H);
    }

    for (int t = 0; t < TT; t++) {
        k_zhbar<<<Gn, 256>>>(lg_W, lg_b, t, t == 0 ? 1 : 0);
        k_ctx<<<Gn / 32, 400>>>(pr_b, t);
        k_gru<<<Gn / 8, 600>>>(b_ih, b_hh, t);
        k_gate<<<Gn, 200>>>();
    }

    k_copy<<<(Gn * H + 255) / 256, 256>>>((float*)d_out, Gn * H);
}